// round 1
// baseline (speedup 1.0000x reference)
#include <cuda_runtime.h>
#include <math.h>

#define H_   192
#define W_   320
#define HW_  (H_*W_)
#define EPS_ 1e-5f
#define INVD (1.0f/507.0f)

#define HB     16              // output rows per CTA
#define NHB    (H_/HB)         // 12 h-blocks
#define CHUNK  14              // disparities per CTA
#define NCHUNK 46              // 46*14 = 644 >= 639 diagonals (d in [-319,319])
#define NT     320             // one thread per column

// ---------------- device scratch (static: no allocation allowed) ----------------
__device__ float4 g_Lp[HW_];           // packed [y][x] = (L0,L1,L2,0)
__device__ float4 g_Rp[HW_];
__device__ float  g_HL1[HW_];          // horizontal 13-tap channel-summed box of L
__device__ float  g_HR1[HW_];          // ... of R
__device__ float  g_HR2[HW_];          // ... of R^2
__device__ float2 g_AB[HW_];           // per (h,v): a = 1/(normR+eps), b = (sumR/507)*a
__device__ float  g_SL[HW_];           // per (h,w): patch sum of L
__device__ float  g_PS[NCHUNK*HW_];    // per-chunk partial best score
__device__ int    g_PV[NCHUNK*HW_];    // per-chunk partial best v
__device__ float  g_scale;             // fx * baseline

// ---------------- prep: pack channels into float4 per pixel ----------------
__global__ void k_pack(const float* __restrict__ L, const float* __restrict__ R) {
    int p = blockIdx.x * blockDim.x + threadIdx.x;
    if (p >= HW_) return;
    g_Lp[p] = make_float4(L[p], L[p + HW_], L[p + 2*HW_], 0.f);
    g_Rp[p] = make_float4(R[p], R[p + HW_], R[p + 2*HW_], 0.f);
}

// ---------------- prep: horizontal 13-tap box sums (zero pad) ----------------
__global__ void k_hbox() {
    int p = blockIdx.x * blockDim.x + threadIdx.x;
    if (p >= HW_) return;
    int x = p % W_;
    float l1 = 0.f, r1 = 0.f, r2 = 0.f;
    #pragma unroll
    for (int dx = -6; dx <= 6; ++dx) {
        int xx = x + dx;
        if ((unsigned)xx < (unsigned)W_) {
            float4 l = g_Lp[p + dx];
            float4 r = g_Rp[p + dx];
            l1 += l.x + l.y + l.z;
            r1 += r.x + r.y + r.z;
            r2 += r.x*r.x + r.y*r.y + r.z*r.z;
        }
    }
    g_HL1[p] = l1; g_HR1[p] = r1; g_HR2[p] = r2;
}

// ---------------- prep: vertical 13-tap + finalize normalization terms ----------------
__global__ void k_vbox() {
    int p = blockIdx.x * blockDim.x + threadIdx.x;
    if (p >= HW_) return;
    int y = p / W_, x = p % W_;
    float sl = 0.f, s1 = 0.f, s2 = 0.f;
    #pragma unroll
    for (int dy = -6; dy <= 6; ++dy) {
        int yy = y + dy;
        if ((unsigned)yy < (unsigned)H_) {
            int q = yy * W_ + x;
            sl += g_HL1[q]; s1 += g_HR1[q]; s2 += g_HR2[q];
        }
    }
    float var = fmaxf(s2 - s1 * s1 * INVD, 0.f);
    float a = 1.f / (sqrtf(var) + EPS_);
    g_AB[p] = make_float2(a, s1 * INVD * a);
    g_SL[p] = sl;
}

// ---------------- prep: fx * baseline (general 4x4 inverse, one thread) ----------------
__global__ void k_const(const float* __restrict__ li,
                        const float* __restrict__ le,
                        const float* __restrict__ re) {
    float a[4][8];
    for (int i = 0; i < 4; ++i)
        for (int j = 0; j < 4; ++j) {
            a[i][j]     = le[i*4 + j];
            a[i][j + 4] = (i == j) ? 1.f : 0.f;
        }
    for (int c = 0; c < 4; ++c) {
        int piv = c; float mx = fabsf(a[c][c]);
        for (int r = c + 1; r < 4; ++r)
            if (fabsf(a[r][c]) > mx) { mx = fabsf(a[r][c]); piv = r; }
        if (piv != c)
            for (int j = 0; j < 8; ++j) { float t = a[c][j]; a[c][j] = a[piv][j]; a[piv][j] = t; }
        float inv = 1.f / a[c][c];
        for (int j = 0; j < 8; ++j) a[c][j] *= inv;
        for (int r = 0; r < 4; ++r) {
            if (r == c) continue;
            float f = a[r][c];
            for (int j = 0; j < 8; ++j) a[r][j] -= f * a[c][j];
        }
    }
    // rel = r_extri @ inv(l_extri); t = rel[:3,3]; baseline = |t|
    float t0 = 0.f, t1 = 0.f, t2 = 0.f;
    for (int k = 0; k < 4; ++k) {
        float ic = a[k][7];  // inv(l_extri)[k][3]
        t0 += re[0*4 + k] * ic;
        t1 += re[1*4 + k] * ic;
        t2 += re[2*4 + k] * ic;
    }
    g_scale = li[0] * sqrtf(t0*t0 + t1*t1 + t2*t2);
}

// ---------------- main: per-diagonal separable box correlation + running argmax ----------------
__global__ void __launch_bounds__(NT) k_main() {
    __shared__ float sBest[HB * W_];
    __shared__ int   sBestV[HB * W_];
    __shared__ float sV[2][W_ + 12];    // 6-pad each side, double-buffered

    const int x     = threadIdx.x;      // column w
    const int chunk = blockIdx.x;
    const int h0    = blockIdx.y * HB;

    for (int i = x; i < HB * W_; i += NT) { sBest[i] = -1e30f; sBestV[i] = 0; }
    if (x < 6) {
        sV[0][x] = 0.f; sV[1][x] = 0.f;
        sV[0][W_ + 6 + x] = 0.f; sV[1][W_ + 6 + x] = 0.f;
    }
    __syncthreads();

    const int d0   = -319 + chunk * CHUNK;
    const int yEnd = h0 + HB + 6;       // last y (exclusive) feeding the window
    int buf = 0;                        // persists across d: keeps double-buffer hazard-free

    for (int di = 0; di < CHUNK; ++di) {
        const int d = d0 + di;
        if (d > 319) break;             // uniform
        const int  v   = x + d;
        const bool vok = ((unsigned)v < (unsigned)W_);

        float ring[13];
        #pragma unroll
        for (int k = 0; k < 13; ++k) ring[k] = 0.f;
        float V = 0.f;

        int y = h0 - 6;
        for (int g = 0; g < 3; ++g) {   // 3*13 = 39 >= HB+12 = 28 iterations
            #pragma unroll
            for (int k = 0; k < 13; ++k) {
                if (y < yEnd) {         // uniform
                    float S = 0.f;
                    if (vok && (unsigned)y < (unsigned)H_) {
                        float4 l = g_Lp[y * W_ + x];
                        float4 r = g_Rp[y * W_ + v];
                        S = l.x * r.x + l.y * r.y + l.z * r.z;
                    }
                    V += S - ring[k];   // vertical 13-row running sum
                    ring[k] = S;
                    const int h = y - 6;
                    if (h >= h0) {      // uniform; h < h0+HB guaranteed by yEnd
                        sV[buf][6 + x] = V;
                        __syncthreads();
                        float cross = 0.f;
                        #pragma unroll
                        for (int t = 0; t < 13; ++t) cross += sV[buf][x + t];
                        if (vok) {
                            const int q = h * W_;
                            float2 ab = g_AB[q + v];
                            float  s  = cross * ab.x - g_SL[q + x] * ab.y;
                            const int idx = (h - h0) * W_ + x;   // thread-exclusive
                            if (s > sBest[idx]) { sBest[idx] = s; sBestV[idx] = v; }
                        }
                        buf ^= 1;
                    }
                }
                ++y;
            }
        }
    }
    __syncthreads();
    for (int i = x; i < HB * W_; i += NT) {
        const int p = (h0 + i / W_) * W_ + (i % W_);   // i%W_ == x here, but keep general
        g_PS[chunk * HW_ + p] = sBest[i];
        g_PV[chunk * HW_ + p] = sBestV[i];
    }
}

// ---------------- merge chunks (first-max semantics) + depth ----------------
__global__ void k_merge(float* __restrict__ out) {
    int p = blockIdx.x * blockDim.x + threadIdx.x;
    if (p >= HW_) return;
    float best = -1e30f; int bv = 0;
    #pragma unroll 4
    for (int c = 0; c < NCHUNK; ++c) {           // ascending d => ascending v: strict > = first max
        float s = g_PS[c * HW_ + p];
        if (s > best) { best = s; bv = g_PV[c * HW_ + p]; }
    }
    int w = p % W_;
    float disp = fabsf((float)bv - (float)w);
    disp = fmaxf(disp, 0.001f);
    out[p] = g_scale / disp;
}

// ---------------- launch ----------------
extern "C" void kernel_launch(void* const* d_in, const int* in_sizes, int n_in,
                              void* d_out, int out_size) {
    const float* L  = (const float*)d_in[0];
    const float* R  = (const float*)d_in[1];
    const float* li = (const float*)d_in[2];
    const float* le = (const float*)d_in[4];
    const float* re = (const float*)d_in[5];

    k_pack <<<(HW_ + 255) / 256, 256>>>(L, R);
    k_hbox <<<(HW_ + 255) / 256, 256>>>();
    k_vbox <<<(HW_ + 255) / 256, 256>>>();
    k_const<<<1, 1>>>(li, le, re);

    dim3 grid(NCHUNK, NHB);
    k_main <<<grid, NT>>>();

    k_merge<<<(HW_ + 255) / 256, 256>>>((float*)d_out);
}

// round 5
// speedup vs baseline: 1.0805x; 1.0805x over previous
#include <cuda_runtime.h>
#include <math.h>

#define H_   192
#define W_   320
#define HW_  (H_*W_)
#define EPS_ 1e-5f
#define INVD (1.0f/507.0f)

#define HB     16               // output rows per CTA
#define NHB    12               // 192/16
#define CHUNK  14               // disparities per half
#define NCX    23               // grid.x: 23*28 = 644 >= 639 diagonals
#define NSLOT  46               // partial slots (2 per CTA-x)
#define NT     640              // threads: (half, x)
#define TROWS  (HB+12)          // 28 tile rows
#define SVW    (W_+12)          // 332

// ---------------- device scratch ----------------
__device__ float  g_hL[HW_];          // horiz 13-tap sum of L (3ch)
__device__ float  g_hR1[HW_];         // of R
__device__ float  g_hR2[HW_];         // of R^2
__device__ float2 g_AB[HW_];          // (h,v): a=1/(normR+eps), b=(sumR/507)*a
__device__ float  g_SL[HW_];          // (h,w): patch sum of L
__device__ float  g_PS[NSLOT*HW_];    // partial best score per slot
__device__ int    g_PV[NSLOT*HW_];    // partial best v per slot
__device__ float  g_scale;            // fx * baseline

// ---------------- prep: horizontal 13-tap box sums (fp32) + scale ----------------
__global__ void k_hbox(const float* __restrict__ L, const float* __restrict__ R,
                       const float* __restrict__ li,
                       const float* __restrict__ le,
                       const float* __restrict__ re) {
    int p = blockIdx.x * blockDim.x + threadIdx.x;
    if (p < HW_) {
        int x = p % W_;
        float hl = 0.f, r1 = 0.f, r2 = 0.f;
        #pragma unroll
        for (int dx = -6; dx <= 6; ++dx) {
            int xx = x + dx;
            if ((unsigned)xx < (unsigned)W_) {
                float l0 = L[p + dx], l1 = L[p + dx + HW_], l2 = L[p + dx + 2*HW_];
                float q0 = R[p + dx], q1 = R[p + dx + HW_], q2 = R[p + dx + 2*HW_];
                hl += l0 + l1 + l2;
                r1 += q0 + q1 + q2;
                r2 += q0*q0 + q1*q1 + q2*q2;
            }
        }
        g_hL[p] = hl; g_hR1[p] = r1; g_hR2[p] = r2;
    }
    if (p == 0) {
        float a[4][8];
        for (int i = 0; i < 4; ++i)
            for (int j = 0; j < 4; ++j) {
                a[i][j]     = le[i*4 + j];
                a[i][j + 4] = (i == j) ? 1.f : 0.f;
            }
        for (int c = 0; c < 4; ++c) {
            int piv = c; float mx = fabsf(a[c][c]);
            for (int r = c + 1; r < 4; ++r)
                if (fabsf(a[r][c]) > mx) { mx = fabsf(a[r][c]); piv = r; }
            if (piv != c)
                for (int j = 0; j < 8; ++j) { float t = a[c][j]; a[c][j] = a[piv][j]; a[piv][j] = t; }
            float inv = 1.f / a[c][c];
            for (int j = 0; j < 8; ++j) a[c][j] *= inv;
            for (int r = 0; r < 4; ++r) {
                if (r == c) continue;
                float f = a[r][c];
                for (int j = 0; j < 8; ++j) a[r][j] -= f * a[c][j];
            }
        }
        float t0 = 0.f, t1 = 0.f, t2 = 0.f;
        for (int k = 0; k < 4; ++k) {
            float ic = a[k][7];
            t0 += re[0*4 + k] * ic;
            t1 += re[1*4 + k] * ic;
            t2 += re[2*4 + k] * ic;
        }
        g_scale = li[0] * sqrtf(t0*t0 + t1*t1 + t2*t2);
    }
}

// ---------------- prep: vertical 13-tap + normalization terms ----------------
__global__ void k_vbox() {
    int p = blockIdx.x * blockDim.x + threadIdx.x;
    if (p >= HW_) return;
    int y = p / W_, x = p % W_;
    float sl = 0.f, s1 = 0.f, s2 = 0.f;
    #pragma unroll
    for (int dy = -6; dy <= 6; ++dy) {
        int yy = y + dy;
        if ((unsigned)yy < (unsigned)H_) {
            int q = yy * W_ + x;
            sl += g_hL[q]; s1 += g_hR1[q]; s2 += g_hR2[q];
        }
    }
    float var = fmaxf(s2 - s1 * s1 * INVD, 0.f);
    float a = 1.f / (sqrtf(var) + EPS_);
    g_AB[p] = make_float2(a, s1 * INVD * a);
    g_SL[p] = sl;
}

// ---------------- main: fp32 smem-tiled separable correlation ----------------
__global__ void __launch_bounds__(NT, 1) k_main(const float* __restrict__ L,
                                                const float* __restrict__ R) {
    extern __shared__ float sm[];
    float* lT = sm;                          // TROWS*W_*3
    float* rT = sm + TROWS*W_*3;             // TROWS*W_*3
    float* sV = sm + 2*TROWS*W_*3;           // 4*SVW (2 halves x 2 parities)

    const int t    = threadIdx.x;
    const int half = t / W_;                 // 0 or 1
    const int x    = t % W_;
    const int h0   = blockIdx.y * HB;

    // threads 0..319 load L tile, 320..639 load R tile (zero-pad outside rows)
    {
        const float* src = half ? R : L;
        float* dst = half ? rT : lT;
        #pragma unroll 4
        for (int r = 0; r < TROWS; ++r) {
            int y = h0 - 6 + r;
            float c0 = 0.f, c1 = 0.f, c2 = 0.f;
            if ((unsigned)y < (unsigned)H_) {
                int p = y * W_ + x;
                c0 = src[p]; c1 = src[p + HW_]; c2 = src[p + 2*HW_];
            }
            int o = (r * W_ + x) * 3;
            dst[o] = c0; dst[o + 1] = c1; dst[o + 2] = c2;
        }
    }
    if (t < 6) {
        #pragma unroll
        for (int b = 0; b < 4; ++b) {
            sV[b * SVW + t] = 0.f;
            sV[b * SVW + W_ + 6 + t] = 0.f;
        }
    }
    __syncthreads();

    float bestS[HB];
    int   bestV[HB];
    #pragma unroll
    for (int j = 0; j < HB; ++j) { bestS[j] = -1e30f; bestV[j] = 0; }

    const int d0 = -319 + blockIdx.x * (2 * CHUNK) + half * CHUNK;

    for (int di = 0; di < CHUNK; ++di) {
        const int  d     = d0 + di;
        const int  v     = x + d;
        const bool vok   = ((unsigned)v < (unsigned)W_);
        const bool valid = vok && (d <= 319);

        float ring[13];
        #pragma unroll
        for (int k = 0; k < 13; ++k) ring[k] = 0.f;
        float V = 0.f;

        #pragma unroll
        for (int step = 0; step < TROWS; ++step) {
            float S = 0.f;
            if (vok) {
                int lo = (step * W_ + x) * 3;
                int ro = (step * W_ + v) * 3;
                S = lT[lo] * rT[ro] + lT[lo+1] * rT[ro+1] + lT[lo+2] * rT[ro+2];
            }
            V += S - ring[step % 13];
            ring[step % 13] = S;
            // V spans tile rows [step-12, step] = image rows [h-6, h+6]
            // for output row h = h0 + step - 12.
            const int hh = step - 12;            // compile-time
            if (hh >= 0) {
                float* buf = sV + (half * 2 + (hh & 1)) * SVW;
                buf[6 + x] = V;
                __syncthreads();
                float cross = 0.f;
                #pragma unroll
                for (int tt = 0; tt < 13; ++tt) cross += buf[x + tt];
                if (valid) {
                    const int q = (h0 + hh) * W_;
                    float2 ab = g_AB[q + v];
                    float  s  = cross * ab.x - g_SL[q + x] * ab.y;
                    if (s > bestS[hh]) { bestS[hh] = s; bestV[hh] = v; }
                }
            }
        }
    }

    const int slot = blockIdx.x * 2 + half;
    const unsigned base = (unsigned)slot * HW_ + (unsigned)h0 * W_ + x;
    #pragma unroll
    for (int j = 0; j < HB; ++j) {
        g_PS[base + j * W_] = bestS[j];
        g_PV[base + j * W_] = bestV[j];
    }
}

// ---------------- merge slots (ascending v => first-max) + depth ----------------
__global__ void k_merge(float* __restrict__ out) {
    int p = blockIdx.x * blockDim.x + threadIdx.x;
    if (p >= HW_) return;
    float best = -1e30f; int bv = 0;
    #pragma unroll 2
    for (int c = 0; c < NSLOT; ++c) {
        float s = g_PS[c * HW_ + p];
        if (s > best) { best = s; bv = g_PV[c * HW_ + p]; }
    }
    int w = p % W_;
    float disp = fabsf((float)bv - (float)w);
    disp = fmaxf(disp, 0.001f);
    out[p] = g_scale / disp;
}

// ---------------- launch ----------------
extern "C" void kernel_launch(void* const* d_in, const int* in_sizes, int n_in,
                              void* d_out, int out_size) {
    const float* L  = (const float*)d_in[0];
    const float* R  = (const float*)d_in[1];
    const float* li = (const float*)d_in[2];
    const float* le = (const float*)d_in[4];
    const float* re = (const float*)d_in[5];

    const int smemBytes = (2 * TROWS * W_ * 3 + 4 * SVW) * 4;   // 220,352 B
    cudaFuncSetAttribute(k_main, cudaFuncAttributeMaxDynamicSharedMemorySize, smemBytes);

    k_hbox<<<(HW_ + 255) / 256, 256>>>(L, R, li, le, re);
    k_vbox<<<(HW_ + 255) / 256, 256>>>();

    dim3 grid(NCX, NHB);
    k_main<<<grid, NT, smemBytes>>>(L, R);

    k_merge<<<(HW_ + 255) / 256, 256>>>((float*)d_out);
}

// round 6
// speedup vs baseline: 2.2184x; 2.0531x over previous
#include <cuda_runtime.h>
#include <math.h>

#define H_    192
#define W_    320
#define HW_   (H_*W_)
#define EPS_  1e-5f
#define INVD  (1.0f/507.0f)

#define HB     16               // output rows per CTA
#define NHB    12               // 192/16
#define NDH    8                // d's per half
#define NDCTA  16               // d's per CTA
#define GRIDX  20               // 20*16 = 320 d values, zero waste
#define NT     640              // threads: (half, x)
#define TROWS  (HB+12)          // 28 tile rows
#define SVW2   (W_+24)          // 344: two 6-padded segments + movable gap

// ---------------- device scratch ----------------
__device__ float  g_hL[HW_];                  // horiz 13-tap sum of L (3ch)
__device__ float  g_hR1[HW_];                 // of R
__device__ float  g_hR2[HW_];                 // of R^2
__device__ float2 g_AB[HW_];                  // (h,v): a, b
__device__ float  g_SL[HW_];                  // (h,w): patch sum of L
__device__ unsigned long long g_best[HW_];    // packed (enc(score) << 32) | (W-1-v)
__device__ float  g_scale;                    // fx * baseline

// ---------------- prep: horizontal 13-tap box sums + scale + best-init ----------------
__global__ void k_hbox(const float* __restrict__ L, const float* __restrict__ R,
                       const float* __restrict__ li,
                       const float* __restrict__ le,
                       const float* __restrict__ re) {
    int p = blockIdx.x * blockDim.x + threadIdx.x;
    if (p < HW_) {
        int x = p % W_;
        float hl = 0.f, r1 = 0.f, r2 = 0.f;
        #pragma unroll
        for (int dx = -6; dx <= 6; ++dx) {
            int xx = x + dx;
            if ((unsigned)xx < (unsigned)W_) {
                float l0 = L[p + dx], l1 = L[p + dx + HW_], l2 = L[p + dx + 2*HW_];
                float q0 = R[p + dx], q1 = R[p + dx + HW_], q2 = R[p + dx + 2*HW_];
                hl += l0 + l1 + l2;
                r1 += q0 + q1 + q2;
                r2 += q0*q0 + q1*q1 + q2*q2;
            }
        }
        g_hL[p] = hl; g_hR1[p] = r1; g_hR2[p] = r2;
        g_best[p] = 0ull;
    }
    if (p == 0) {
        float a[4][8];
        for (int i = 0; i < 4; ++i)
            for (int j = 0; j < 4; ++j) {
                a[i][j]     = le[i*4 + j];
                a[i][j + 4] = (i == j) ? 1.f : 0.f;
            }
        for (int c = 0; c < 4; ++c) {
            int piv = c; float mx = fabsf(a[c][c]);
            for (int r = c + 1; r < 4; ++r)
                if (fabsf(a[r][c]) > mx) { mx = fabsf(a[r][c]); piv = r; }
            if (piv != c)
                for (int j = 0; j < 8; ++j) { float t = a[c][j]; a[c][j] = a[piv][j]; a[piv][j] = t; }
            float inv = 1.f / a[c][c];
            for (int j = 0; j < 8; ++j) a[c][j] *= inv;
            for (int r = 0; r < 4; ++r) {
                if (r == c) continue;
                float f = a[r][c];
                for (int j = 0; j < 8; ++j) a[r][j] -= f * a[c][j];
            }
        }
        float t0 = 0.f, t1 = 0.f, t2 = 0.f;
        for (int k = 0; k < 4; ++k) {
            float ic = a[k][7];
            t0 += re[0*4 + k] * ic;
            t1 += re[1*4 + k] * ic;
            t2 += re[2*4 + k] * ic;
        }
        g_scale = li[0] * sqrtf(t0*t0 + t1*t1 + t2*t2);
    }
}

// ---------------- prep: vertical 13-tap + normalization terms ----------------
__global__ void k_vbox() {
    int p = blockIdx.x * blockDim.x + threadIdx.x;
    if (p >= HW_) return;
    int y = p / W_, x = p % W_;
    float sl = 0.f, s1 = 0.f, s2 = 0.f;
    #pragma unroll
    for (int dy = -6; dy <= 6; ++dy) {
        int yy = y + dy;
        if ((unsigned)yy < (unsigned)H_) {
            int q = yy * W_ + x;
            sl += g_hL[q]; s1 += g_hR1[q]; s2 += g_hR2[q];
        }
    }
    float var = fmaxf(s2 - s1 * s1 * INVD, 0.f);
    float a = 1.f / (sqrtf(var) + EPS_);
    g_AB[p] = make_float2(a, s1 * INVD * a);
    g_SL[p] = sl;
}

// ---------------- main: wrap-packed diagonals, zero idle threads ----------------
__global__ void __launch_bounds__(NT, 1) k_main(const float* __restrict__ L,
                                                const float* __restrict__ R) {
    extern __shared__ float sm[];
    float* lT = sm;                          // TROWS*W_*3
    float* rT = sm + TROWS*W_*3;             // TROWS*W_*3
    float* sV = sm + 2*TROWS*W_*3;           // 4*SVW2 (2 halves x 2 parities)

    const int t    = threadIdx.x;
    const int half = t / W_;                 // 0 or 1
    const int x    = t % W_;
    const int h0   = blockIdx.y * HB;

    // cooperative tile load: half 0 -> L, half 1 -> R (zero-pad outside rows)
    {
        const float* src = half ? R : L;
        float* dst = half ? rT : lT;
        #pragma unroll 4
        for (int r = 0; r < TROWS; ++r) {
            int y = h0 - 6 + r;
            float c0 = 0.f, c1 = 0.f, c2 = 0.f;
            if ((unsigned)y < (unsigned)H_) {
                int p = y * W_ + x;
                c0 = src[p]; c1 = src[p + HW_]; c2 = src[p + 2*HW_];
            }
            int o = (r * W_ + x) * 3;
            dst[o] = c0; dst[o + 1] = c1; dst[o + 2] = c2;
        }
    }
    // static zeros: [0,6) and [W_+18, W_+24) of every buffer (never overwritten)
    if (t < 6) {
        #pragma unroll
        for (int b = 0; b < 4; ++b) {
            sV[b * SVW2 + t] = 0.f;
            sV[b * SVW2 + W_ + 18 + t] = 0.f;
        }
    }
    __syncthreads();

    float bestS[HB];
    int   bestV[HB];
    #pragma unroll
    for (int j = 0; j < HB; ++j) { bestS[j] = -1e30f; bestV[j] = 0; }

    float* bufA = sV + (half * 2 + 0) * SVW2;   // parity 0
    float* bufB = sV + (half * 2 + 1) * SVW2;   // parity 1

    const int d0 = blockIdx.x * NDCTA + half * NDH;

    for (int di = 0; di < NDH; ++di) {
        const int d = d0 + di;                 // d in [0, 320)
        const int c = W_ - d;                  // wrap column (c=320 when d=0)
        int v = x + d; if (v >= W_) v -= W_;   // v = (x+d) mod W_, always valid
        // write position: segment 1 [6, 6+c) for x<c; segment 2 [18+c, 338) for x>=c
        const int wpos  = (x < c) ? (6 + x) : (18 + x);
        const int rbase = wpos - 6;

        float ring[13];
        #pragma unroll
        for (int k = 0; k < 13; ++k) ring[k] = 0.f;
        float V = 0.f;

        #pragma unroll
        for (int step = 0; step < TROWS; ++step) {
            {
                int lo = (step * W_ + x) * 3;
                int ro = (step * W_ + v) * 3;
                float S = lT[lo] * rT[ro] + lT[lo+1] * rT[ro+1] + lT[lo+2] * rT[ro+2];
                V += S - ring[step % 13];
                ring[step % 13] = S;
            }
            // V spans image rows [h-6, h+6] for output row h = h0 + step - 12
            const int hh = step - 12;            // compile-time
            if (hh >= 0) {
                float* buf = (hh & 1) ? bufB : bufA;
                buf[wpos] = V;
                // re-zero the movable 12-wide gap [c+6, c+18) once per (d, parity),
                // under the same barrier as this row's stores (race-free).
                if (hh == 0 && x < 12) bufA[c + 6 + x] = 0.f;
                if (hh == 1 && x < 12) bufB[c + 6 + x] = 0.f;
                __syncthreads();
                float cross = 0.f;
                #pragma unroll
                for (int tt = 0; tt < 13; ++tt) cross += buf[rbase + tt];
                const int q = (h0 + hh) * W_;
                float2 ab = g_AB[q + v];
                float  s  = cross * ab.x - g_SL[q + x] * ab.y;
                if (s > bestS[hh]) { bestS[hh] = s; bestV[hh] = v; }
            }
        }
    }

    // one packed atomicMax per output pixel per (CTA, half)
    #pragma unroll
    for (int j = 0; j < HB; ++j) {
        unsigned eb = __float_as_uint(bestS[j]);
        eb = (eb & 0x80000000u) ? ~eb : (eb | 0x80000000u);   // order-preserving
        unsigned long long u = ((unsigned long long)eb << 32)
                             | (unsigned)(W_ - 1 - bestV[j]); // ties -> smallest v
        atomicMax(&g_best[(h0 + j) * W_ + x], u);
    }
}

// ---------------- depth ----------------
__global__ void k_depth(float* __restrict__ out) {
    int p = blockIdx.x * blockDim.x + threadIdx.x;
    if (p >= HW_) return;
    unsigned long long u = g_best[p];
    int bv = W_ - 1 - (int)(u & 0xFFFFFFFFull);
    int w = p % W_;
    float disp = fabsf((float)bv - (float)w);
    disp = fmaxf(disp, 0.001f);
    out[p] = g_scale / disp;
}

// ---------------- launch ----------------
extern "C" void kernel_launch(void* const* d_in, const int* in_sizes, int n_in,
                              void* d_out, int out_size) {
    const float* L  = (const float*)d_in[0];
    const float* R  = (const float*)d_in[1];
    const float* li = (const float*)d_in[2];
    const float* le = (const float*)d_in[4];
    const float* re = (const float*)d_in[5];

    const int smemBytes = (2 * TROWS * W_ * 3 + 4 * SVW2) * 4;   // 220,544 B
    cudaFuncSetAttribute(k_main, cudaFuncAttributeMaxDynamicSharedMemorySize, smemBytes);

    k_hbox<<<(HW_ + 255) / 256, 256>>>(L, R, li, le, re);
    k_vbox<<<(HW_ + 255) / 256, 256>>>();

    dim3 grid(GRIDX, NHB);
    k_main<<<grid, NT, smemBytes>>>(L, R);

    k_depth<<<(HW_ + 255) / 256, 256>>>((float*)d_out);
}

// round 7
// speedup vs baseline: 2.3077x; 1.0403x over previous
#include <cuda_runtime.h>
#include <math.h>

#define H_    192
#define W_    320
#define HW_   (H_*W_)
#define EPS_  1e-5f
#define INVD  (1.0f/507.0f)

#define HB     16               // output rows per CTA
#define NHB    12               // 192/16
#define NDH    8                // d's per half
#define NDCTA  16               // d's per CTA
#define GRIDX  20               // 20*16 = 320 d values, zero waste
#define NT     640              // threads: (half, x)
#define TROWS  (HB+12)          // 28 tile rows
#define PLW    348              // plane row width: 6+320+12(gap)+10 pad

// ---------------- device scratch ----------------
__device__ float  g_hL[HW_];                  // horiz 13-tap sum of L (3ch)
__device__ float  g_hR1[HW_];                 // of R
__device__ float  g_hR2[HW_];                 // of R^2
__device__ float2 g_AB[HW_];                  // (h,v): a, b
__device__ float  g_SL[HW_];                  // (h,w): patch sum of L
__device__ unsigned long long g_best[HW_];    // packed (enc(score) << 32) | (W-1-v)
__device__ float  g_scale;                    // fx * baseline

// ---------------- prep: horizontal 13-tap box sums + scale + best-init ----------------
__global__ void k_hbox(const float* __restrict__ L, const float* __restrict__ R,
                       const float* __restrict__ li,
                       const float* __restrict__ le,
                       const float* __restrict__ re) {
    int p = blockIdx.x * blockDim.x + threadIdx.x;
    if (p < HW_) {
        int x = p % W_;
        float hl = 0.f, r1 = 0.f, r2 = 0.f;
        #pragma unroll
        for (int dx = -6; dx <= 6; ++dx) {
            int xx = x + dx;
            if ((unsigned)xx < (unsigned)W_) {
                float l0 = L[p + dx], l1 = L[p + dx + HW_], l2 = L[p + dx + 2*HW_];
                float q0 = R[p + dx], q1 = R[p + dx + HW_], q2 = R[p + dx + 2*HW_];
                hl += l0 + l1 + l2;
                r1 += q0 + q1 + q2;
                r2 += q0*q0 + q1*q1 + q2*q2;
            }
        }
        g_hL[p] = hl; g_hR1[p] = r1; g_hR2[p] = r2;
        g_best[p] = 0ull;
    }
    if (p == 0) {
        float a[4][8];
        for (int i = 0; i < 4; ++i)
            for (int j = 0; j < 4; ++j) {
                a[i][j]     = le[i*4 + j];
                a[i][j + 4] = (i == j) ? 1.f : 0.f;
            }
        for (int c = 0; c < 4; ++c) {
            int piv = c; float mx = fabsf(a[c][c]);
            for (int r = c + 1; r < 4; ++r)
                if (fabsf(a[r][c]) > mx) { mx = fabsf(a[r][c]); piv = r; }
            if (piv != c)
                for (int j = 0; j < 8; ++j) { float t = a[c][j]; a[c][j] = a[piv][j]; a[piv][j] = t; }
            float inv = 1.f / a[c][c];
            for (int j = 0; j < 8; ++j) a[c][j] *= inv;
            for (int r = 0; r < 4; ++r) {
                if (r == c) continue;
                float f = a[r][c];
                for (int j = 0; j < 8; ++j) a[r][j] -= f * a[c][j];
            }
        }
        float t0 = 0.f, t1 = 0.f, t2 = 0.f;
        for (int k = 0; k < 4; ++k) {
            float ic = a[k][7];
            t0 += re[0*4 + k] * ic;
            t1 += re[1*4 + k] * ic;
            t2 += re[2*4 + k] * ic;
        }
        g_scale = li[0] * sqrtf(t0*t0 + t1*t1 + t2*t2);
    }
}

// ---------------- prep: vertical 13-tap + normalization terms ----------------
__global__ void k_vbox() {
    int p = blockIdx.x * blockDim.x + threadIdx.x;
    if (p >= HW_) return;
    int y = p / W_, x = p % W_;
    float sl = 0.f, s1 = 0.f, s2 = 0.f;
    #pragma unroll
    for (int dy = -6; dy <= 6; ++dy) {
        int yy = y + dy;
        if ((unsigned)yy < (unsigned)H_) {
            int q = yy * W_ + x;
            sl += g_hL[q]; s1 += g_hR1[q]; s2 += g_hR2[q];
        }
    }
    float var = fmaxf(s2 - s1 * s1 * INVD, 0.f);
    float a = 1.f / (sqrtf(var) + EPS_);
    g_AB[p] = make_float2(a, s1 * INVD * a);
    g_SL[p] = sl;
}

// ---------------- main: step-outer / d-inner, 16 barriers per CTA ----------------
__global__ void __launch_bounds__(NT, 1) k_main(const float* __restrict__ L,
                                                const float* __restrict__ R) {
    extern __shared__ float sm[];
    float* rT = sm;                          // TROWS*W_*3 (R tile only)
    float* pl = sm + TROWS*W_*3;             // 32 plane rows * PLW

    const int t    = threadIdx.x;
    const int half = t / W_;                 // 0 or 1
    const int x    = t % W_;
    const int h0   = blockIdx.y * HB;
    const int d0   = blockIdx.x * NDCTA + half * NDH;

    // cooperative R tile load (zero-pad outside rows)
    for (int i = t; i < TROWS * W_; i += NT) {
        int r = i / W_, xx = i % W_;
        int y = h0 - 6 + r;
        float c0 = 0.f, c1 = 0.f, c2 = 0.f;
        if ((unsigned)y < (unsigned)H_) {
            int p = y * W_ + xx;
            c0 = R[p]; c1 = R[p + HW_]; c2 = R[p + 2*HW_];
        }
        int o = i * 3;
        rT[o] = c0; rT[o + 1] = c1; rT[o + 2] = c2;
    }
    // zero entire plane once: covers static pads AND all fixed wrap gaps
    for (int i = t; i < 32 * PLW; i += NT) pl[i] = 0.f;

    // per-d constants (fixed for the whole kernel)
    int vv[NDH], wp[NDH];
    #pragma unroll
    for (int d = 0; d < NDH; ++d) {
        int dd = d0 + d;
        int v = x + dd; if (v >= W_) v -= W_;
        vv[d] = v;
        int c = W_ - dd;                      // wrap column
        wp[d] = (x < c) ? (6 + x) : (18 + x); // seg1 [6,6+c), seg2 [18+c,338)
    }

    // hoist SL (d-independent)
    float SLr[HB];
    #pragma unroll
    for (int j = 0; j < HB; ++j) SLr[j] = g_SL[(h0 + j) * W_ + x];

    float bestS[HB]; int bestV[HB];
    #pragma unroll
    for (int j = 0; j < HB; ++j) { bestS[j] = -1e30f; bestV[j] = 0; }

    float ring[NDH][13];
    float V[NDH];
    #pragma unroll
    for (int d = 0; d < NDH; ++d) {
        V[d] = 0.f;
        #pragma unroll
        for (int k = 0; k < 13; ++k) ring[d][k] = 0.f;
    }

    __syncthreads();

    #pragma unroll
    for (int step = 0; step < TROWS; ++step) {
        // L row from gmem (L2-resident, coalesced, shared across all 8 d's)
        int y = h0 - 6 + step;
        float l0 = 0.f, l1 = 0.f, l2 = 0.f;
        if ((unsigned)y < (unsigned)H_) {
            int p = y * W_ + x;
            l0 = L[p]; l1 = L[p + HW_]; l2 = L[p + 2*HW_];
        }
        #pragma unroll
        for (int d = 0; d < NDH; ++d) {
            const float* rp = &rT[(step * W_ + vv[d]) * 3];
            float S = l0 * rp[0] + l1 * rp[1] + l2 * rp[2];   // 0 when y invalid
            V[d] += S - ring[d][step % 13];
            ring[d][step % 13] = S;
        }
        // V spans image rows [h-6, h+6] for output row h = h0 + step - 12
        const int hh = step - 12;             // compile-time
        if (hh >= 0) {
            const int pb = ((half * 2 + (hh & 1)) * NDH) * PLW;
            #pragma unroll
            for (int d = 0; d < NDH; ++d)
                pl[pb + d * PLW + wp[d]] = V[d];
            // prefetch AB for this row (latency hidden across the barrier)
            float2 ABr[NDH];
            #pragma unroll
            for (int d = 0; d < NDH; ++d)
                ABr[d] = g_AB[(h0 + hh) * W_ + vv[d]];
            __syncthreads();
            #pragma unroll
            for (int d = 0; d < NDH; ++d) {
                const float* q = &pl[pb + d * PLW + wp[d] - 6];
                float cr = q[0] + q[1] + q[2] + q[3] + q[4] + q[5] + q[6]
                         + q[7] + q[8] + q[9] + q[10] + q[11] + q[12];
                float s = cr * ABr[d].x - SLr[hh] * ABr[d].y;
                if (s > bestS[hh]) { bestS[hh] = s; bestV[hh] = vv[d]; }
            }
        }
    }

    // one packed atomicMax per output pixel per (CTA, half)
    #pragma unroll
    for (int j = 0; j < HB; ++j) {
        unsigned eb = __float_as_uint(bestS[j]);
        eb = (eb & 0x80000000u) ? ~eb : (eb | 0x80000000u);   // order-preserving
        unsigned long long u = ((unsigned long long)eb << 32)
                             | (unsigned)(W_ - 1 - bestV[j]); // ties -> smallest v
        atomicMax(&g_best[(h0 + j) * W_ + x], u);
    }
}

// ---------------- depth ----------------
__global__ void k_depth(float* __restrict__ out) {
    int p = blockIdx.x * blockDim.x + threadIdx.x;
    if (p >= HW_) return;
    unsigned long long u = g_best[p];
    int bv = W_ - 1 - (int)(u & 0xFFFFFFFFull);
    int w = p % W_;
    float disp = fabsf((float)bv - (float)w);
    disp = fmaxf(disp, 0.001f);
    out[p] = g_scale / disp;
}

// ---------------- launch ----------------
extern "C" void kernel_launch(void* const* d_in, const int* in_sizes, int n_in,
                              void* d_out, int out_size) {
    const float* L  = (const float*)d_in[0];
    const float* R  = (const float*)d_in[1];
    const float* li = (const float*)d_in[2];
    const float* le = (const float*)d_in[4];
    const float* re = (const float*)d_in[5];

    const int smemBytes = (TROWS * W_ * 3 + 32 * PLW) * 4;   // 152,064 B
    cudaFuncSetAttribute(k_main, cudaFuncAttributeMaxDynamicSharedMemorySize, smemBytes);

    k_hbox<<<(HW_ + 255) / 256, 256>>>(L, R, li, le, re);
    k_vbox<<<(HW_ + 255) / 256, 256>>>();

    dim3 grid(GRIDX, NHB);
    k_main<<<grid, NT, smemBytes>>>(L, R);

    k_depth<<<(HW_ + 255) / 256, 256>>>((float*)d_out);
}